// round 1
// baseline (speedup 1.0000x reference)
#include <cuda_runtime.h>
#include <math.h>

#define NTOK 16384
#define HDIM 2048
#define FPN  1024
#define SPN  1024
#define NCOLS 2050   // FP + SP + 2

// Scratch (static device allocations only — no cudaMalloc allowed)
__device__ float g_logits[(size_t)NTOK * 1024];   // 64 MB
__device__ int   g_list[2][NTOK];
__device__ int   g_cnt[2];
__device__ float g_endprob[NTOK];

__global__ void init_kernel() {
    if (threadIdx.x < 2) g_cnt[threadIdx.x] = 0;
}

// One warp per token: end-head dot product + sigmoid + class compaction.
__global__ void __launch_bounds__(256) classify_kernel(
    const float* __restrict__ X, const int* __restrict__ pY,
    const float* __restrict__ W_end, const float* __restrict__ b_end)
{
    int gwarp = (blockIdx.x * blockDim.x + threadIdx.x) >> 5;
    int lane  = threadIdx.x & 31;
    if (gwarp >= NTOK) return;
    const float4* x = reinterpret_cast<const float4*>(X) + (size_t)gwarp * (HDIM / 4);
    const float4* w = reinterpret_cast<const float4*>(W_end);
    float acc = 0.f;
    #pragma unroll 4
    for (int i = lane; i < HDIM / 4; i += 32) {
        float4 a = x[i]; float4 b = w[i];
        acc = fmaf(a.x, b.x, acc); acc = fmaf(a.y, b.y, acc);
        acc = fmaf(a.z, b.z, acc); acc = fmaf(a.w, b.w, acc);
    }
    #pragma unroll
    for (int o = 16; o > 0; o >>= 1) acc += __shfl_xor_sync(0xffffffffu, acc, o);
    if (lane == 0) {
        float logit = acc + b_end[0];
        float ep = 1.f / (1.f + expf(-logit));
        g_endprob[gwarp] = ep;
        int c = pY[gwarp];
        if (c == 1 || c == 2) {
            int pos = atomicAdd(&g_cnt[c - 1], 1);
            g_list[c - 1][pos] = gwarp;
        }
    }
}

// Gathered fp32 GEMM: logits[token][n] = X[token] . W[n] + bias[n]
// Tile 64 tokens x 64 outputs, BK=16, 256 threads, 4x4 micro-tile.
__global__ void __launch_bounds__(256) gemm_kernel(
    const float* __restrict__ X, const float* __restrict__ W,
    const float* __restrict__ bias, int sel)
{
    __shared__ float As[16][68];   // [k][m], row stride 68*4=272B (16B aligned)
    __shared__ float Bs[16][68];   // [k][n]
    int cnt = g_cnt[sel];
    int mt = blockIdx.y;
    if (mt * 64 >= cnt) return;
    int n0 = blockIdx.x * 64;
    const int* list = g_list[sel];
    int tid  = threadIdx.x;
    int lrow = tid >> 2;   // 0..63
    int lk4  = tid & 3;    // which float4 of the 16-wide k-chunk
    int mrow = mt * 64 + lrow;
    int tok  = (mrow < cnt) ? list[mrow] : -1;
    const float4* xr = reinterpret_cast<const float4*>(X) + (size_t)(tok < 0 ? 0 : tok) * (HDIM / 4);
    const float4* wr = reinterpret_cast<const float4*>(W) + (size_t)(n0 + lrow) * (HDIM / 4);

    int tx = tid & 15, ty = tid >> 4;
    float acc[4][4];
    #pragma unroll
    for (int i = 0; i < 4; i++)
        #pragma unroll
        for (int j = 0; j < 4; j++) acc[i][j] = 0.f;

    for (int k0 = 0; k0 < HDIM / 4; k0 += 4) {
        float4 av = make_float4(0.f, 0.f, 0.f, 0.f);
        if (tok >= 0) av = xr[k0 + lk4];
        float4 bv = wr[k0 + lk4];
        As[lk4 * 4 + 0][lrow] = av.x; As[lk4 * 4 + 1][lrow] = av.y;
        As[lk4 * 4 + 2][lrow] = av.z; As[lk4 * 4 + 3][lrow] = av.w;
        Bs[lk4 * 4 + 0][lrow] = bv.x; Bs[lk4 * 4 + 1][lrow] = bv.y;
        Bs[lk4 * 4 + 2][lrow] = bv.z; Bs[lk4 * 4 + 3][lrow] = bv.w;
        __syncthreads();
        #pragma unroll
        for (int kk = 0; kk < 16; kk++) {
            float4 a = *reinterpret_cast<const float4*>(&As[kk][ty * 4]);
            float4 b = *reinterpret_cast<const float4*>(&Bs[kk][tx * 4]);
            float ar[4] = {a.x, a.y, a.z, a.w};
            float br[4] = {b.x, b.y, b.z, b.w};
            #pragma unroll
            for (int i = 0; i < 4; i++)
                #pragma unroll
                for (int j = 0; j < 4; j++)
                    acc[i][j] = fmaf(ar[i], br[j], acc[i][j]);
        }
        __syncthreads();
    }

    #pragma unroll
    for (int i = 0; i < 4; i++) {
        int mg = mt * 64 + ty * 4 + i;
        if (mg < cnt) {
            int t2 = list[mg];
            float* dst = g_logits + (size_t)t2 * 1024 + n0 + tx * 4;
            float4 o;
            o.x = acc[i][0] + bias[n0 + tx * 4 + 0];
            o.y = acc[i][1] + bias[n0 + tx * 4 + 1];
            o.z = acc[i][2] + bias[n0 + tx * 4 + 2];
            o.w = acc[i][3] + bias[n0 + tx * 4 + 3];
            *reinterpret_cast<float4*>(dst) = o;
        }
    }
}

// One block per token: softmax over the active head, scatter into output row,
// and log_prob via logsumexp.
__global__ void __launch_bounds__(256) finalize_kernel(
    const int* __restrict__ pY, const int* __restrict__ Y,
    float* __restrict__ out)
{
    int n = blockIdx.x;
    int cls = pY[n];
    float ep = g_endprob[n];
    float* logp = out;                                 // [NTOK] first
    float* row  = out + NTOK + (size_t)n * NCOLS;      // then [NTOK][2050]
    if (cls == 0) {
        if (threadIdx.x == 0) {
            row[0] = ep; row[1] = ep;
            logp[n] = logf(ep);
        }
        return;
    }
    const float* lg = g_logits + (size_t)n * 1024;
    int tid = threadIdx.x;
    float v[4];
    float vmax = -1e30f;
    #pragma unroll
    for (int i = 0; i < 4; i++) { v[i] = lg[tid + i * 256]; vmax = fmaxf(vmax, v[i]); }

    __shared__ float sred[8];
    #pragma unroll
    for (int o = 16; o > 0; o >>= 1) vmax = fmaxf(vmax, __shfl_xor_sync(0xffffffffu, vmax, o));
    if ((tid & 31) == 0) sred[tid >> 5] = vmax;
    __syncthreads();
    float m = fmaxf(fmaxf(fmaxf(sred[0], sred[1]), fmaxf(sred[2], sred[3])),
                    fmaxf(fmaxf(sred[4], sred[5]), fmaxf(sred[6], sred[7])));
    __syncthreads();

    float e[4]; float s = 0.f;
    #pragma unroll
    for (int i = 0; i < 4; i++) { e[i] = expf(v[i] - m); s += e[i]; }
    #pragma unroll
    for (int o = 16; o > 0; o >>= 1) s += __shfl_xor_sync(0xffffffffu, s, o);
    if ((tid & 31) == 0) sred[tid >> 5] = s;
    __syncthreads();
    float sum = sred[0] + sred[1] + sred[2] + sred[3]
              + sred[4] + sred[5] + sred[6] + sred[7];

    float nonend = 1.f - ep;
    float scale = nonend / sum;
    int off = (cls == 1) ? 2 : (2 + FPN);
    #pragma unroll
    for (int i = 0; i < 4; i++) row[off + tid + i * 256] = e[i] * scale;

    int idx = Y[n] - 2 - ((cls == 2) ? FPN : 0);
    idx = min(max(idx, 0), 1023);
    if (tid == (idx & 255)) {
        int i = idx >> 8;
        logp[n] = (v[i] - m - logf(sum)) + logf(nonend);
    }
}

extern "C" void kernel_launch(void* const* d_in, const int* in_sizes, int n_in,
                              void* d_out, int out_size)
{
    const float* X     = (const float*)d_in[0];
    const int*   pY    = (const int*)  d_in[1];
    const int*   Y     = (const int*)  d_in[2];
    const float* W_end = (const float*)d_in[3];
    const float* b_end = (const float*)d_in[4];
    const float* W_hcw = (const float*)d_in[5];
    const float* b_hcw = (const float*)d_in[6];
    const float* W_roo = (const float*)d_in[7];
    const float* b_roo = (const float*)d_in[8];
    float* out = (float*)d_out;

    // Zero entire output (prob matrix is mostly structural zeros; buffer is poisoned).
    cudaMemsetAsync(d_out, 0, (size_t)out_size * sizeof(float), 0);
    init_kernel<<<1, 32>>>();
    classify_kernel<<<NTOK / 8, 256>>>(X, pY, W_end, b_end);
    dim3 grid(FPN / 64, NTOK / 64);   // 16 col tiles x 256 row tiles (excess tiles exit)
    gemm_kernel<<<grid, 256>>>(X, W_hcw, b_hcw, 0);
    gemm_kernel<<<grid, 256>>>(X, W_roo, b_roo, 1);
    finalize_kernel<<<NTOK, 256>>>(pY, Y, out);
}

// round 3
// speedup vs baseline: 1.8661x; 1.8661x over previous
#include <cuda_runtime.h>
#include <cuda_bf16.h>
#include <cstdint>
#include <math.h>

#define NTOK 16384
#define HDIM 2048
#define FPN  1024
#define NCOLS 2050

#define BM 128
#define BN 128
#define BK 32
#define KIT (HDIM / BK)   // 64

// smem stage layout (bf16 tiles, rows padded to 40 elems = 80B)
#define A_HI 0
#define A_LO 10240
#define B_HI 20480
#define B_LO 30720
#define STG  40960
#define SM_TOTAL (2 * STG)   // 81920 B

// scratch (static device mem only)
__device__ float g_logits[(size_t)NTOK * 1024];   // 64 MB
__device__ int   g_list[2][NTOK];
__device__ int   g_cnt[2];
__device__ float g_endprob[NTOK];

__device__ __forceinline__ uint32_t smem_u32(const void* p) {
    uint32_t a;
    asm("{ .reg .u64 t; cvta.to.shared.u64 t, %1; cvt.u32.u64 %0, t; }" : "=r"(a) : "l"(p));
    return a;
}

#define LDSM4(r, addr) \
    asm volatile("ldmatrix.sync.aligned.m8n8.x4.shared.b16 {%0,%1,%2,%3}, [%4];" \
        : "=r"((r)[0]), "=r"((r)[1]), "=r"((r)[2]), "=r"((r)[3]) : "r"(addr))

#define MMA_BF16(c, a, b0, b1) \
    asm volatile("mma.sync.aligned.m16n8k16.row.col.f32.bf16.bf16.f32 " \
        "{%0,%1,%2,%3}, {%4,%5,%6,%7}, {%8,%9}, {%0,%1,%2,%3};" \
        : "+f"((c)[0]), "+f"((c)[1]), "+f"((c)[2]), "+f"((c)[3]) \
        : "r"((a)[0]), "r"((a)[1]), "r"((a)[2]), "r"((a)[3]), "r"(b0), "r"(b1))

__device__ __forceinline__ void split2(float x, float y, uint32_t& hi, uint32_t& lo) {
    __nv_bfloat16 hx = __float2bfloat16_rn(x);
    __nv_bfloat16 hy = __float2bfloat16_rn(y);
    __nv_bfloat16 lx = __float2bfloat16_rn(x - __bfloat162float(hx));
    __nv_bfloat16 ly = __float2bfloat16_rn(y - __bfloat162float(hy));
    __nv_bfloat162 h2 = __halves2bfloat162(hx, hy);
    __nv_bfloat162 l2 = __halves2bfloat162(lx, ly);
    hi = *reinterpret_cast<uint32_t*>(&h2);
    lo = *reinterpret_cast<uint32_t*>(&l2);
}

// ---------------- kernels ----------------
__global__ void init_kernel() {
    if (threadIdx.x < 2) g_cnt[threadIdx.x] = 0;
}

__global__ void __launch_bounds__(256) classify_kernel(
    const float* __restrict__ X, const int* __restrict__ pY,
    const float* __restrict__ W_end, const float* __restrict__ b_end)
{
    int gwarp = (blockIdx.x * blockDim.x + threadIdx.x) >> 5;
    int lane  = threadIdx.x & 31;
    if (gwarp >= NTOK) return;
    const float4* x = reinterpret_cast<const float4*>(X) + (size_t)gwarp * (HDIM / 4);
    const float4* w = reinterpret_cast<const float4*>(W_end);
    float acc = 0.f;
    #pragma unroll 4
    for (int i = lane; i < HDIM / 4; i += 32) {
        float4 a = x[i]; float4 b = w[i];
        acc = fmaf(a.x, b.x, acc); acc = fmaf(a.y, b.y, acc);
        acc = fmaf(a.z, b.z, acc); acc = fmaf(a.w, b.w, acc);
    }
    #pragma unroll
    for (int o = 16; o > 0; o >>= 1) acc += __shfl_xor_sync(0xffffffffu, acc, o);
    if (lane == 0) {
        float logit = acc + b_end[0];
        float ep = 1.f / (1.f + expf(-logit));
        g_endprob[gwarp] = ep;
        int c = pY[gwarp];
        if (c == 1 || c == 2) {
            int pos = atomicAdd(&g_cnt[c - 1], 1);
            g_list[c - 1][pos] = gwarp;
        }
    }
}

// Gathered GEMM via mma.sync bf16 3x-split: logits[tok][n] = X[tok].W[n] + bias[n]
__global__ void __launch_bounds__(256, 1) gemm_mma_kernel(
    const float* __restrict__ X,
    const float* __restrict__ W0, const float* __restrict__ b0,
    const float* __restrict__ W1, const float* __restrict__ b1)
{
    extern __shared__ char smem[];
    int sel = blockIdx.z;
    int cnt = g_cnt[sel];
    int mtB = blockIdx.y * BM;
    if (mtB >= cnt) return;
    const float* W    = sel ? W1 : W0;
    const float* bias = sel ? b1 : b0;
    const int*   list = g_list[sel];
    int n0  = blockIdx.x * BN;
    int tid = threadIdx.x;
    int lane = tid & 31, wid = tid >> 5;
    int wm = wid >> 2, wn = wid & 3;     // warp grid 2 x 4, warp tile 64 x 32
    uint32_t sb = smem_u32(smem);

    // per-thread gmem load slots: c4 = float4 index in 32-wide k chunk, rows
    int c4 = tid & 7;
    int rA[4], tokA[4];
    #pragma unroll
    for (int j = 0; j < 4; j++) {
        rA[j] = (tid >> 3) + j * 32;
        int m = mtB + rA[j];
        tokA[j] = list[m < cnt ? m : cnt - 1];
    }

    // ldmatrix per-lane address bases
    int sub = lane >> 3, r8 = lane & 7;
    uint32_t aBase = sb + (uint32_t)((wm * 64 + (sub & 1) * 8 + r8) * 80 + ((sub >> 1) * 8) * 2);
    uint32_t bBase = sb + B_HI + (uint32_t)((wn * 32 + (sub >> 1) * 8 + r8) * 80 + ((sub & 1) * 8) * 2);

    float acc[4][4][4];
    #pragma unroll
    for (int i = 0; i < 4; i++)
        #pragma unroll
        for (int j = 0; j < 4; j++)
            #pragma unroll
            for (int q = 0; q < 4; q++) acc[i][j][q] = 0.f;

    float4 aR[4], bR[4];
    // prefetch iter 0
    #pragma unroll
    for (int j = 0; j < 4; j++) {
        aR[j] = *(const float4*)(X + (size_t)tokA[j] * HDIM + c4 * 4);
        bR[j] = *(const float4*)(W + (size_t)(n0 + rA[j]) * HDIM + c4 * 4);
    }

    for (int it = 0; it < KIT; it++) {
        uint32_t stOff = (uint32_t)((it & 1) * STG);
        // convert + store to smem stage
        #pragma unroll
        for (int j = 0; j < 4; j++) {
            uint32_t off = (uint32_t)(rA[j] * 80 + c4 * 8);
            uint32_t h0, l0, h1, l1;
            split2(aR[j].x, aR[j].y, h0, l0);
            split2(aR[j].z, aR[j].w, h1, l1);
            *(uint2*)(smem + stOff + A_HI + off) = make_uint2(h0, h1);
            *(uint2*)(smem + stOff + A_LO + off) = make_uint2(l0, l1);
            split2(bR[j].x, bR[j].y, h0, l0);
            split2(bR[j].z, bR[j].w, h1, l1);
            *(uint2*)(smem + stOff + B_HI - 20480 + 20480 + off) = make_uint2(h0, h1);
            *(uint2*)(smem + stOff + B_LO + off) = make_uint2(l0, l1);
        }
        __syncthreads();

        if (it + 1 < KIT) {
            int k0 = (it + 1) * BK;
            #pragma unroll
            for (int j = 0; j < 4; j++) {
                aR[j] = *(const float4*)(X + (size_t)tokA[j] * HDIM + k0 + c4 * 4);
                bR[j] = *(const float4*)(W + (size_t)(n0 + rA[j]) * HDIM + k0 + c4 * 4);
            }
        }

        #pragma unroll
        for (int kk = 0; kk < 2; kk++) {
            uint32_t aHi[4][4], aLo[4][4], bHi[2][4], bLo[2][4];
            #pragma unroll
            for (int mt = 0; mt < 4; mt++) {
                LDSM4(aHi[mt], aBase + stOff + (uint32_t)(mt * 1280 + kk * 32));
                LDSM4(aLo[mt], aBase + stOff + A_LO + (uint32_t)(mt * 1280 + kk * 32));
            }
            #pragma unroll
            for (int p = 0; p < 2; p++) {
                LDSM4(bHi[p], bBase + stOff + (uint32_t)(p * 1280 + kk * 32));
                LDSM4(bLo[p], bBase + stOff + 10240u + (uint32_t)(p * 1280 + kk * 32));
            }
            // pass 1: hi*hi
            #pragma unroll
            for (int mt = 0; mt < 4; mt++)
                #pragma unroll
                for (int nt = 0; nt < 4; nt++)
                    MMA_BF16(acc[mt][nt], aHi[mt], bHi[nt >> 1][(nt & 1) * 2], bHi[nt >> 1][(nt & 1) * 2 + 1]);
            // pass 2: lo*hi
            #pragma unroll
            for (int mt = 0; mt < 4; mt++)
                #pragma unroll
                for (int nt = 0; nt < 4; nt++)
                    MMA_BF16(acc[mt][nt], aLo[mt], bHi[nt >> 1][(nt & 1) * 2], bHi[nt >> 1][(nt & 1) * 2 + 1]);
            // pass 3: hi*lo
            #pragma unroll
            for (int mt = 0; mt < 4; mt++)
                #pragma unroll
                for (int nt = 0; nt < 4; nt++)
                    MMA_BF16(acc[mt][nt], aHi[mt], bLo[nt >> 1][(nt & 1) * 2], bLo[nt >> 1][(nt & 1) * 2 + 1]);
        }
    }

    // epilogue: write logits straight from accumulators (+bias)
    int colB = wn * 32 + (lane & 3) * 2;
    float2 bv[4];
    #pragma unroll
    for (int nt = 0; nt < 4; nt++)
        bv[nt] = *(const float2*)(bias + n0 + colB + nt * 8);
    #pragma unroll
    for (int mt = 0; mt < 4; mt++) {
        int r0 = mtB + wm * 64 + mt * 16 + (lane >> 2);
        #pragma unroll
        for (int h = 0; h < 2; h++) {
            int row = r0 + h * 8;
            if (row < cnt) {
                int tok = list[row];
                float* dst = g_logits + (size_t)tok * 1024 + n0 + colB;
                #pragma unroll
                for (int nt = 0; nt < 4; nt++) {
                    float2 o;
                    o.x = acc[mt][nt][h * 2 + 0] + bv[nt].x;
                    o.y = acc[mt][nt][h * 2 + 1] + bv[nt].y;
                    *(float2*)(dst + nt * 8) = o;
                }
            }
        }
    }
}

// per-token softmax + full-row output write (no memset needed)
__global__ void __launch_bounds__(256) finalize_kernel(
    const int* __restrict__ pY, const int* __restrict__ Y,
    float* __restrict__ out)
{
    int n = blockIdx.x;
    int cls = pY[n];
    float ep = g_endprob[n];
    float* logp = out;
    float* row  = out + NTOK + (size_t)n * NCOLS;
    int tid = threadIdx.x;

    if (cls == 0) {
        #pragma unroll
        for (int i = 0; i < 8; i++) row[2 + tid + i * 256] = 0.f;
        if (tid == 0) { row[0] = ep; row[1] = ep; logp[n] = logf(ep); }
        return;
    }

    const float* lg = g_logits + (size_t)n * 1024;
    float v[4]; float vmax = -1e30f;
    #pragma unroll
    for (int i = 0; i < 4; i++) { v[i] = lg[tid + i * 256]; vmax = fmaxf(vmax, v[i]); }

    __shared__ float sred[8];
    #pragma unroll
    for (int o = 16; o > 0; o >>= 1) vmax = fmaxf(vmax, __shfl_xor_sync(0xffffffffu, vmax, o));
    if ((tid & 31) == 0) sred[tid >> 5] = vmax;
    __syncthreads();
    float m = fmaxf(fmaxf(fmaxf(sred[0], sred[1]), fmaxf(sred[2], sred[3])),
                    fmaxf(fmaxf(sred[4], sred[5]), fmaxf(sred[6], sred[7])));
    __syncthreads();

    float e[4]; float s = 0.f;
    #pragma unroll
    for (int i = 0; i < 4; i++) { e[i] = expf(v[i] - m); s += e[i]; }
    #pragma unroll
    for (int o = 16; o > 0; o >>= 1) s += __shfl_xor_sync(0xffffffffu, s, o);
    if ((tid & 31) == 0) sred[tid >> 5] = s;
    __syncthreads();
    float sum = sred[0] + sred[1] + sred[2] + sred[3]
              + sred[4] + sred[5] + sred[6] + sred[7];

    float nonend = 1.f - ep;
    float scale = nonend / sum;
    int off  = (cls == 1) ? 2 : (2 + FPN);
    int zoff = (cls == 1) ? (2 + FPN) : 2;
    #pragma unroll
    for (int i = 0; i < 4; i++) row[off + tid + i * 256] = e[i] * scale;
    #pragma unroll
    for (int i = 0; i < 4; i++) row[zoff + tid + i * 256] = 0.f;
    if (tid == 0) { row[0] = 0.f; row[1] = 0.f; }

    int idx = Y[n] - 2 - ((cls == 2) ? FPN : 0);
    idx = min(max(idx, 0), 1023);
    if (tid == (idx & 255)) {
        int i = idx >> 8;
        logp[n] = (v[i] - m - logf(sum)) + logf(nonend);
    }
}

extern "C" void kernel_launch(void* const* d_in, const int* in_sizes, int n_in,
                              void* d_out, int out_size)
{
    const float* X     = (const float*)d_in[0];
    const int*   pY    = (const int*)  d_in[1];
    const int*   Y     = (const int*)  d_in[2];
    const float* W_end = (const float*)d_in[3];
    const float* b_end = (const float*)d_in[4];
    const float* W_hcw = (const float*)d_in[5];
    const float* b_hcw = (const float*)d_in[6];
    const float* W_roo = (const float*)d_in[7];
    const float* b_roo = (const float*)d_in[8];
    float* out = (float*)d_out;

    cudaFuncSetAttribute(gemm_mma_kernel,
                         cudaFuncAttributeMaxDynamicSharedMemorySize, SM_TOTAL);

    init_kernel<<<1, 32>>>();
    classify_kernel<<<NTOK / 8, 256>>>(X, pY, W_end, b_end);
    dim3 grid(FPN / BN, NTOK / BM, 2);   // (8, 128, 2); inactive m-tiles exit early
    gemm_mma_kernel<<<grid, 256, SM_TOTAL>>>(X, W_hcw, b_hcw, W_roo, b_roo);
    finalize_kernel<<<NTOK, 256>>>(pY, Y, out);
}

// round 4
// speedup vs baseline: 2.6817x; 1.4371x over previous
#include <cuda_runtime.h>
#include <cuda_bf16.h>
#include <cstdint>
#include <math.h>

#define NTOK 16384
#define HDIM 2048
#define FPN  1024
#define NCOLS 2050

#define BM 128
#define BN 128
#define BK 32
#define KIT (HDIM / BK)   // 64
#define STAGES 3

// per-stage smem layout (bf16 tiles, rows = 32 data elems padded to 40 = 80B)
#define A_HI 0
#define A_LO 10240
#define B_HI 20480
#define B_LO 30720
#define STG  40960
#define SM_TOTAL (STAGES * STG)   // 122880 B

// scratch (static device mem only)
__device__ float          g_logits[(size_t)NTOK * 1024];        // 64 MB
__device__ __nv_bfloat16  g_Xhi[(size_t)NTOK * HDIM];           // 64 MB
__device__ __nv_bfloat16  g_Xlo[(size_t)NTOK * HDIM];           // 64 MB
__device__ __nv_bfloat16  g_Whi[(size_t)2 * FPN * HDIM];        // 8 MB
__device__ __nv_bfloat16  g_Wlo[(size_t)2 * FPN * HDIM];        // 8 MB
__device__ int   g_list[2][NTOK];
__device__ int   g_cnt[2];
__device__ float g_endprob[NTOK];

__device__ __forceinline__ uint32_t smem_u32(const void* p) {
    uint32_t a;
    asm("{ .reg .u64 t; cvta.to.shared.u64 t, %1; cvt.u32.u64 %0, t; }" : "=r"(a) : "l"(p));
    return a;
}

#define CP16(dst, src) \
    asm volatile("cp.async.cg.shared.global [%0], [%1], 16;" :: "r"(dst), "l"(src))
#define CP_COMMIT() asm volatile("cp.async.commit_group;" ::: "memory")
#define CP_WAIT1()  asm volatile("cp.async.wait_group 1;" ::: "memory")

#define LDSM4(r, addr) \
    asm volatile("ldmatrix.sync.aligned.m8n8.x4.shared.b16 {%0,%1,%2,%3}, [%4];" \
        : "=r"((r)[0]), "=r"((r)[1]), "=r"((r)[2]), "=r"((r)[3]) : "r"(addr))

#define MMA_BF16(c, a, b0, b1) \
    asm volatile("mma.sync.aligned.m16n8k16.row.col.f32.bf16.bf16.f32 " \
        "{%0,%1,%2,%3}, {%4,%5,%6,%7}, {%8,%9}, {%0,%1,%2,%3};" \
        : "+f"((c)[0]), "+f"((c)[1]), "+f"((c)[2]), "+f"((c)[3]) \
        : "r"((a)[0]), "r"((a)[1]), "r"((a)[2]), "r"((a)[3]), "r"(b0), "r"(b1))

__device__ __forceinline__ void split4(float4 v, uint2& hi, uint2& lo) {
    __nv_bfloat16 hx = __float2bfloat16_rn(v.x), hy = __float2bfloat16_rn(v.y);
    __nv_bfloat16 hz = __float2bfloat16_rn(v.z), hw = __float2bfloat16_rn(v.w);
    __nv_bfloat16 lx = __float2bfloat16_rn(v.x - __bfloat162float(hx));
    __nv_bfloat16 ly = __float2bfloat16_rn(v.y - __bfloat162float(hy));
    __nv_bfloat16 lz = __float2bfloat16_rn(v.z - __bfloat162float(hz));
    __nv_bfloat16 lw = __float2bfloat16_rn(v.w - __bfloat162float(hw));
    __nv_bfloat162 h0 = __halves2bfloat162(hx, hy), h1 = __halves2bfloat162(hz, hw);
    __nv_bfloat162 l0 = __halves2bfloat162(lx, ly), l1 = __halves2bfloat162(lz, lw);
    hi = make_uint2(*(uint32_t*)&h0, *(uint32_t*)&h1);
    lo = make_uint2(*(uint32_t*)&l0, *(uint32_t*)&l1);
}

// ---------------- kernels ----------------
__global__ void init_kernel() {
    if (threadIdx.x < 2) g_cnt[threadIdx.x] = 0;
}

// One warp per token: end-head dot + sigmoid + compaction + X hi/lo conversion.
__global__ void __launch_bounds__(256) classify_convert_kernel(
    const float* __restrict__ X, const int* __restrict__ pY,
    const float* __restrict__ W_end, const float* __restrict__ b_end)
{
    int gwarp = (blockIdx.x * blockDim.x + threadIdx.x) >> 5;
    int lane  = threadIdx.x & 31;
    if (gwarp >= NTOK) return;
    const float4* x = reinterpret_cast<const float4*>(X) + (size_t)gwarp * (HDIM / 4);
    const float4* w = reinterpret_cast<const float4*>(W_end);
    uint2* xh = reinterpret_cast<uint2*>(g_Xhi + (size_t)gwarp * HDIM);
    uint2* xl = reinterpret_cast<uint2*>(g_Xlo + (size_t)gwarp * HDIM);
    float acc = 0.f;
    #pragma unroll 4
    for (int i = lane; i < HDIM / 4; i += 32) {
        float4 a = x[i]; float4 b = w[i];
        acc = fmaf(a.x, b.x, acc); acc = fmaf(a.y, b.y, acc);
        acc = fmaf(a.z, b.z, acc); acc = fmaf(a.w, b.w, acc);
        uint2 hi, lo; split4(a, hi, lo);
        xh[i] = hi; xl[i] = lo;
    }
    #pragma unroll
    for (int o = 16; o > 0; o >>= 1) acc += __shfl_xor_sync(0xffffffffu, acc, o);
    if (lane == 0) {
        float logit = acc + b_end[0];
        float ep = 1.f / (1.f + expf(-logit));
        g_endprob[gwarp] = ep;
        int c = pY[gwarp];
        if (c == 1 || c == 2) {
            int pos = atomicAdd(&g_cnt[c - 1], 1);
            g_list[c - 1][pos] = gwarp;
        }
    }
}

__global__ void __launch_bounds__(256) wconvert_kernel(
    const float* __restrict__ W0, const float* __restrict__ W1)
{
    int i = blockIdx.x * blockDim.x + threadIdx.x;   // float4 index, 2*FPN*HDIM/4 total
    const int half = FPN * HDIM / 4;
    const float4* src = (i < half) ? (const float4*)W0 + i : (const float4*)W1 + (i - half);
    float4 v = *src;
    uint2 hi, lo; split4(v, hi, lo);
    reinterpret_cast<uint2*>(g_Whi)[i] = hi;
    reinterpret_cast<uint2*>(g_Wlo)[i] = lo;
}

// Gathered bf16 3x-split GEMM, cp.async 3-stage pipeline.
__global__ void __launch_bounds__(256) gemm_mma_kernel(
    const float* __restrict__ b0, const float* __restrict__ b1)
{
    extern __shared__ char smem[];
    int sel = blockIdx.z;
    int cnt = g_cnt[sel];
    int mtB = blockIdx.y * BM;
    if (mtB >= cnt) return;
    const float* bias = sel ? b1 : b0;
    const int*   list = g_list[sel];
    int n0  = blockIdx.x * BN;
    int tid = threadIdx.x;
    int lane = tid & 31, wid = tid >> 5;
    int wm = wid >> 2, wn = wid & 3;     // warp grid 2 x 4; warp tile 64 x 32
    uint32_t sb = smem_u32(smem);

    // load-slot mapping: 4 x 16B chunks per 64B row, 2 rows per thread per tile kind
    int c = tid & 3;
    int r0 = tid >> 2;                   // 0..63; rows r0 and r0+64
    const __nv_bfloat16* pAhi[2];
    const __nv_bfloat16* pAlo[2];
    const __nv_bfloat16* pBhi[2];
    const __nv_bfloat16* pBlo[2];
    #pragma unroll
    for (int j = 0; j < 2; j++) {
        int r = r0 + j * 64;
        int m = mtB + r;
        int tok = list[m < cnt ? m : cnt - 1];
        pAhi[j] = g_Xhi + (size_t)tok * HDIM + c * 8;
        pAlo[j] = g_Xlo + (size_t)tok * HDIM + c * 8;
        size_t wo = (size_t)sel * FPN * HDIM + (size_t)(n0 + r) * HDIM + c * 8;
        pBhi[j] = g_Whi + wo;
        pBlo[j] = g_Wlo + wo;
    }
    uint32_t dOff = (uint32_t)(r0 * 80 + c * 16);

    // ldmatrix per-lane bases
    int sub = lane >> 3, r8 = lane & 7;
    uint32_t aBase = sb + (uint32_t)((wm * 64 + (sub & 1) * 8 + r8) * 80 + ((sub >> 1) * 8) * 2);
    uint32_t bBase = sb + B_HI + (uint32_t)((wn * 32 + (sub >> 1) * 8 + r8) * 80 + ((sub & 1) * 8) * 2);

    float acc[4][4][4];
    #pragma unroll
    for (int i = 0; i < 4; i++)
        #pragma unroll
        for (int j = 0; j < 4; j++)
            #pragma unroll
            for (int q = 0; q < 4; q++) acc[i][j][q] = 0.f;

    // stage-issue helper (macro to keep pointers in regs)
    #define ISSUE_STAGE(stage, k0)                                              \
        do {                                                                    \
            uint32_t st_ = sb + (uint32_t)(stage) * STG;                        \
            _Pragma("unroll")                                                   \
            for (int j_ = 0; j_ < 2; j_++) {                                    \
                uint32_t d_ = st_ + dOff + (uint32_t)(j_ * 64 * 80);            \
                CP16(d_ + A_HI, pAhi[j_] + (k0));                               \
                CP16(d_ + A_LO, pAlo[j_] + (k0));                               \
                CP16(d_ + B_HI, pBhi[j_] + (k0));                               \
                CP16(d_ + B_LO, pBlo[j_] + (k0));                               \
            }                                                                   \
            CP_COMMIT();                                                        \
        } while (0)

    ISSUE_STAGE(0, 0);
    ISSUE_STAGE(1, BK);

    for (int it = 0; it < KIT; it++) {
        CP_WAIT1();
        __syncthreads();
        int ld = it + STAGES - 1;
        if (ld < KIT) {
            ISSUE_STAGE(ld % STAGES, ld * BK);
        } else {
            CP_COMMIT();   // keep group accounting uniform
        }
        uint32_t stOff = (uint32_t)((it % STAGES)) * STG;

        #pragma unroll
        for (int kk = 0; kk < 2; kk++) {
            uint32_t aHi[4][4], aLo[4][4], bHi[2][4], bLo[2][4];
            #pragma unroll
            for (int mt = 0; mt < 4; mt++) {
                LDSM4(aHi[mt], aBase + stOff + (uint32_t)(mt * 1280 + kk * 32));
                LDSM4(aLo[mt], aBase + stOff + A_LO + (uint32_t)(mt * 1280 + kk * 32));
            }
            #pragma unroll
            for (int p = 0; p < 2; p++) {
                LDSM4(bHi[p], bBase + stOff + (uint32_t)(p * 1280 + kk * 32));
                LDSM4(bLo[p], bBase + stOff + 10240u + (uint32_t)(p * 1280 + kk * 32));
            }
            #pragma unroll
            for (int mt = 0; mt < 4; mt++)
                #pragma unroll
                for (int nt = 0; nt < 4; nt++)
                    MMA_BF16(acc[mt][nt], aHi[mt], bHi[nt >> 1][(nt & 1) * 2], bHi[nt >> 1][(nt & 1) * 2 + 1]);
            #pragma unroll
            for (int mt = 0; mt < 4; mt++)
                #pragma unroll
                for (int nt = 0; nt < 4; nt++)
                    MMA_BF16(acc[mt][nt], aLo[mt], bHi[nt >> 1][(nt & 1) * 2], bHi[nt >> 1][(nt & 1) * 2 + 1]);
            #pragma unroll
            for (int mt = 0; mt < 4; mt++)
                #pragma unroll
                for (int nt = 0; nt < 4; nt++)
                    MMA_BF16(acc[mt][nt], aHi[mt], bLo[nt >> 1][(nt & 1) * 2], bLo[nt >> 1][(nt & 1) * 2 + 1]);
        }
    }

    // epilogue: logits = acc + bias, scattered by token
    int colB = wn * 32 + (lane & 3) * 2;
    float2 bv[4];
    #pragma unroll
    for (int nt = 0; nt < 4; nt++)
        bv[nt] = *(const float2*)(bias + n0 + colB + nt * 8);
    #pragma unroll
    for (int mt = 0; mt < 4; mt++) {
        int rr = mtB + wm * 64 + mt * 16 + (lane >> 2);
        #pragma unroll
        for (int h = 0; h < 2; h++) {
            int row = rr + h * 8;
            if (row < cnt) {
                int tok = list[row];
                float* dst = g_logits + (size_t)tok * 1024 + n0 + colB;
                #pragma unroll
                for (int nt = 0; nt < 4; nt++) {
                    float2 o;
                    o.x = acc[mt][nt][h * 2 + 0] + bv[nt].x;
                    o.y = acc[mt][nt][h * 2 + 1] + bv[nt].y;
                    *(float2*)(dst + nt * 8) = o;
                }
            }
        }
    }
    #undef ISSUE_STAGE
}

// per-token softmax + full-row output write (no memset needed)
__global__ void __launch_bounds__(256) finalize_kernel(
    const int* __restrict__ pY, const int* __restrict__ Y,
    float* __restrict__ out)
{
    int n = blockIdx.x;
    int cls = pY[n];
    float ep = g_endprob[n];
    float* logp = out;
    float* row  = out + NTOK + (size_t)n * NCOLS;
    int tid = threadIdx.x;

    if (cls == 0) {
        #pragma unroll
        for (int i = 0; i < 8; i++) row[2 + tid + i * 256] = 0.f;
        if (tid == 0) { row[0] = ep; row[1] = ep; logp[n] = logf(ep); }
        return;
    }

    const float* lg = g_logits + (size_t)n * 1024;
    float v[4]; float vmax = -1e30f;
    #pragma unroll
    for (int i = 0; i < 4; i++) { v[i] = lg[tid + i * 256]; vmax = fmaxf(vmax, v[i]); }

    __shared__ float sred[8];
    #pragma unroll
    for (int o = 16; o > 0; o >>= 1) vmax = fmaxf(vmax, __shfl_xor_sync(0xffffffffu, vmax, o));
    if ((tid & 31) == 0) sred[tid >> 5] = vmax;
    __syncthreads();
    float m = fmaxf(fmaxf(fmaxf(sred[0], sred[1]), fmaxf(sred[2], sred[3])),
                    fmaxf(fmaxf(sred[4], sred[5]), fmaxf(sred[6], sred[7])));
    __syncthreads();

    float e[4]; float s = 0.f;
    #pragma unroll
    for (int i = 0; i < 4; i++) { e[i] = expf(v[i] - m); s += e[i]; }
    #pragma unroll
    for (int o = 16; o > 0; o >>= 1) s += __shfl_xor_sync(0xffffffffu, s, o);
    if ((tid & 31) == 0) sred[tid >> 5] = s;
    __syncthreads();
    float sum = sred[0] + sred[1] + sred[2] + sred[3]
              + sred[4] + sred[5] + sred[6] + sred[7];

    float nonend = 1.f - ep;
    float scale = nonend / sum;
    int off  = (cls == 1) ? 2 : (2 + FPN);
    int zoff = (cls == 1) ? (2 + FPN) : 2;
    #pragma unroll
    for (int i = 0; i < 4; i++) row[off + tid + i * 256] = e[i] * scale;
    #pragma unroll
    for (int i = 0; i < 4; i++) row[zoff + tid + i * 256] = 0.f;
    if (tid == 0) { row[0] = 0.f; row[1] = 0.f; }

    int idx = Y[n] - 2 - ((cls == 2) ? FPN : 0);
    idx = min(max(idx, 0), 1023);
    if (tid == (idx & 255)) {
        int i = idx >> 8;
        logp[n] = (v[i] - m - logf(sum)) + logf(nonend);
    }
}

extern "C" void kernel_launch(void* const* d_in, const int* in_sizes, int n_in,
                              void* d_out, int out_size)
{
    const float* X     = (const float*)d_in[0];
    const int*   pY    = (const int*)  d_in[1];
    const int*   Y     = (const int*)  d_in[2];
    const float* W_end = (const float*)d_in[3];
    const float* b_end = (const float*)d_in[4];
    const float* W_hcw = (const float*)d_in[5];
    const float* b_hcw = (const float*)d_in[6];
    const float* W_roo = (const float*)d_in[7];
    const float* b_roo = (const float*)d_in[8];
    float* out = (float*)d_out;

    cudaFuncSetAttribute(gemm_mma_kernel,
                         cudaFuncAttributeMaxDynamicSharedMemorySize, SM_TOTAL);

    init_kernel<<<1, 32>>>();
    wconvert_kernel<<<2 * FPN * HDIM / 4 / 256, 256>>>(W_hcw, W_roo);
    classify_convert_kernel<<<NTOK / 8, 256>>>(X, pY, W_end, b_end);
    dim3 grid(FPN / BN, NTOK / BM, 2);   // inactive m-tiles exit early
    gemm_mma_kernel<<<grid, 256, SM_TOTAL>>>(b_hcw, b_roo);
    finalize_kernel<<<NTOK, 256>>>(pY, Y, out);
}

// round 5
// speedup vs baseline: 3.4252x; 1.2772x over previous
#include <cuda_runtime.h>
#include <cuda_bf16.h>
#include <cstdint>
#include <math.h>

#define NTOK 16384
#define HDIM 2048
#define FPN  1024
#define NCOLS 2050

#define BM 128
#define BN 128
#define BK 32
#define KIT (HDIM / BK)   // 64
#define STAGES 3

// per-stage smem layout: 4 tiles x 128 rows x 64B (XOR-swizzled 16B chunks)
#define A_HI 0
#define A_LO 8192
#define B_HI 16384
#define B_LO 24576
#define STG  32768
#define SM_TOTAL (STAGES * STG)   // 98304 B -> 2 CTAs/SM

// scratch (static device mem only)
__device__ float          g_logits[(size_t)NTOK * 1024];        // 64 MB
__device__ __nv_bfloat16  g_Xhi[(size_t)NTOK * HDIM];           // 64 MB
__device__ __nv_bfloat16  g_Xlo[(size_t)NTOK * HDIM];           // 64 MB
__device__ __nv_bfloat16  g_Whi[(size_t)2 * FPN * HDIM];        // 8 MB
__device__ __nv_bfloat16  g_Wlo[(size_t)2 * FPN * HDIM];        // 8 MB
__device__ int   g_list[2][NTOK];
__device__ int   g_cnt[2];
__device__ float g_endprob[NTOK];

__device__ __forceinline__ uint32_t smem_u32(const void* p) {
    uint32_t a;
    asm("{ .reg .u64 t; cvta.to.shared.u64 t, %1; cvt.u32.u64 %0, t; }" : "=r"(a) : "l"(p));
    return a;
}

#define CP16(dst, src) \
    asm volatile("cp.async.cg.shared.global [%0], [%1], 16;" :: "r"(dst), "l"(src))
#define CP_COMMIT() asm volatile("cp.async.commit_group;" ::: "memory")
#define CP_WAIT1()  asm volatile("cp.async.wait_group 1;" ::: "memory")

#define LDSM4(r, addr) \
    asm volatile("ldmatrix.sync.aligned.m8n8.x4.shared.b16 {%0,%1,%2,%3}, [%4];" \
        : "=r"((r)[0]), "=r"((r)[1]), "=r"((r)[2]), "=r"((r)[3]) : "r"(addr))

#define MMA_BF16(c, a, b0, b1) \
    asm volatile("mma.sync.aligned.m16n8k16.row.col.f32.bf16.bf16.f32 " \
        "{%0,%1,%2,%3}, {%4,%5,%6,%7}, {%8,%9}, {%0,%1,%2,%3};" \
        : "+f"((c)[0]), "+f"((c)[1]), "+f"((c)[2]), "+f"((c)[3]) \
        : "r"((a)[0]), "r"((a)[1]), "r"((a)[2]), "r"((a)[3]), "r"(b0), "r"(b1))

// swizzled byte offset inside one 128x64B tile: chunk index XOR'd by (row>>1)&3
__device__ __forceinline__ uint32_t swz(uint32_t row, uint32_t chunk) {
    return row * 64u + ((chunk ^ ((row >> 1) & 3u)) << 4);
}

__device__ __forceinline__ void split4(float4 v, uint2& hi, uint2& lo) {
    __nv_bfloat16 hx = __float2bfloat16_rn(v.x), hy = __float2bfloat16_rn(v.y);
    __nv_bfloat16 hz = __float2bfloat16_rn(v.z), hw = __float2bfloat16_rn(v.w);
    __nv_bfloat16 lx = __float2bfloat16_rn(v.x - __bfloat162float(hx));
    __nv_bfloat16 ly = __float2bfloat16_rn(v.y - __bfloat162float(hy));
    __nv_bfloat16 lz = __float2bfloat16_rn(v.z - __bfloat162float(hz));
    __nv_bfloat16 lw = __float2bfloat16_rn(v.w - __bfloat162float(hw));
    __nv_bfloat162 h0 = __halves2bfloat162(hx, hy), h1 = __halves2bfloat162(hz, hw);
    __nv_bfloat162 l0 = __halves2bfloat162(lx, ly), l1 = __halves2bfloat162(lz, lw);
    hi = make_uint2(*(uint32_t*)&h0, *(uint32_t*)&h1);
    lo = make_uint2(*(uint32_t*)&l0, *(uint32_t*)&l1);
}

// ---------------- kernels ----------------
__global__ void init_kernel() {
    if (threadIdx.x < 2) g_cnt[threadIdx.x] = 0;
}

__global__ void __launch_bounds__(256) classify_convert_kernel(
    const float* __restrict__ X, const int* __restrict__ pY,
    const float* __restrict__ W_end, const float* __restrict__ b_end)
{
    int gwarp = (blockIdx.x * blockDim.x + threadIdx.x) >> 5;
    int lane  = threadIdx.x & 31;
    if (gwarp >= NTOK) return;
    const float4* x = reinterpret_cast<const float4*>(X) + (size_t)gwarp * (HDIM / 4);
    const float4* w = reinterpret_cast<const float4*>(W_end);
    uint2* xh = reinterpret_cast<uint2*>(g_Xhi + (size_t)gwarp * HDIM);
    uint2* xl = reinterpret_cast<uint2*>(g_Xlo + (size_t)gwarp * HDIM);
    float acc = 0.f;
    #pragma unroll 4
    for (int i = lane; i < HDIM / 4; i += 32) {
        float4 a = x[i]; float4 b = w[i];
        acc = fmaf(a.x, b.x, acc); acc = fmaf(a.y, b.y, acc);
        acc = fmaf(a.z, b.z, acc); acc = fmaf(a.w, b.w, acc);
        uint2 hi, lo; split4(a, hi, lo);
        xh[i] = hi; xl[i] = lo;
    }
    #pragma unroll
    for (int o = 16; o > 0; o >>= 1) acc += __shfl_xor_sync(0xffffffffu, acc, o);
    if (lane == 0) {
        float logit = acc + b_end[0];
        float ep = 1.f / (1.f + expf(-logit));
        g_endprob[gwarp] = ep;
        int c = pY[gwarp];
        if (c == 1 || c == 2) {
            int pos = atomicAdd(&g_cnt[c - 1], 1);
            g_list[c - 1][pos] = gwarp;
        }
    }
}

__global__ void __launch_bounds__(256) wconvert_kernel(
    const float* __restrict__ W0, const float* __restrict__ W1)
{
    int i = blockIdx.x * blockDim.x + threadIdx.x;
    const int half = FPN * HDIM / 4;
    const float4* src = (i < half) ? (const float4*)W0 + i : (const float4*)W1 + (i - half);
    float4 v = *src;
    uint2 hi, lo; split4(v, hi, lo);
    reinterpret_cast<uint2*>(g_Whi)[i] = hi;
    reinterpret_cast<uint2*>(g_Wlo)[i] = lo;
}

// Gathered bf16 3x-split GEMM; cp.async 3-stage pipeline; 2 CTAs/SM.
__global__ void __launch_bounds__(256, 2) gemm_mma_kernel(
    const float* __restrict__ b0, const float* __restrict__ b1)
{
    extern __shared__ char smem[];
    int sel = blockIdx.z;
    int cnt = g_cnt[sel];
    int mtB = blockIdx.y * BM;
    if (mtB >= cnt) return;
    const float* bias = sel ? b1 : b0;
    const int*   list = g_list[sel];
    int n0  = blockIdx.x * BN;
    int tid = threadIdx.x;
    int lane = tid & 31, wid = tid >> 5;
    int wm = wid >> 2, wn = wid & 3;     // warp grid 2 x 4; warp tile 64 x 32
    uint32_t sb = smem_u32(smem);

    // load slots: chunk c (16B) of 64B row; rows r0 and r0+64
    int c = tid & 3;
    int r0 = tid >> 2;
    const __nv_bfloat16* pAhi[2];
    const __nv_bfloat16* pAlo[2];
    const __nv_bfloat16* pBhi[2];
    const __nv_bfloat16* pBlo[2];
    uint32_t dOff[2];
    #pragma unroll
    for (int j = 0; j < 2; j++) {
        int r = r0 + j * 64;
        int m = mtB + r;
        int tok = list[m < cnt ? m : cnt - 1];
        pAhi[j] = g_Xhi + (size_t)tok * HDIM + c * 8;
        pAlo[j] = g_Xlo + (size_t)tok * HDIM + c * 8;
        size_t wo = (size_t)sel * FPN * HDIM + (size_t)(n0 + r) * HDIM + c * 8;
        pBhi[j] = g_Whi + wo;
        pBlo[j] = g_Wlo + wo;
        dOff[j] = swz((uint32_t)r, (uint32_t)c);
    }

    // ldmatrix lane geometry
    int sub = lane >> 3, r8 = lane & 7;
    int aRowL = (sub & 1) * 8 + r8;   // + wm*64 + mt*16
    int aChk  = sub >> 1;             // 16B chunk within 32B kk-block
    int bRowL = (sub >> 1) * 8 + r8;  // + wn*32 + p*16
    int bChk  = sub & 1;

    float acc[4][4][4];
    #pragma unroll
    for (int i = 0; i < 4; i++)
        #pragma unroll
        for (int j = 0; j < 4; j++)
            #pragma unroll
            for (int q = 0; q < 4; q++) acc[i][j][q] = 0.f;

    #define ISSUE_STAGE(stage, k0)                                              \
        do {                                                                    \
            uint32_t st_ = sb + (uint32_t)(stage) * STG;                        \
            _Pragma("unroll")                                                   \
            for (int j_ = 0; j_ < 2; j_++) {                                    \
                uint32_t d_ = st_ + dOff[j_];                                   \
                CP16(d_ + A_HI, pAhi[j_] + (k0));                               \
                CP16(d_ + A_LO, pAlo[j_] + (k0));                               \
                CP16(d_ + B_HI, pBhi[j_] + (k0));                               \
                CP16(d_ + B_LO, pBlo[j_] + (k0));                               \
            }                                                                   \
            CP_COMMIT();                                                        \
        } while (0)

    ISSUE_STAGE(0, 0);
    ISSUE_STAGE(1, BK);

    for (int it = 0; it < KIT; it++) {
        CP_WAIT1();
        __syncthreads();
        int ld = it + STAGES - 1;
        if (ld < KIT) {
            ISSUE_STAGE(ld % STAGES, ld * BK);
        } else {
            CP_COMMIT();
        }
        uint32_t stOff = sb + (uint32_t)(it % STAGES) * STG;

        #pragma unroll
        for (int kk = 0; kk < 2; kk++) {
            uint32_t aHi[4][4], aLo[4][4], bHi[2][4], bLo[2][4];
            #pragma unroll
            for (int mt = 0; mt < 4; mt++) {
                uint32_t r = (uint32_t)(wm * 64 + mt * 16 + aRowL);
                uint32_t o = swz(r, (uint32_t)(kk * 2 + aChk));
                LDSM4(aHi[mt], stOff + A_HI + o);
                LDSM4(aLo[mt], stOff + A_LO + o);
            }
            #pragma unroll
            for (int p = 0; p < 2; p++) {
                uint32_t r = (uint32_t)(wn * 32 + p * 16 + bRowL);
                uint32_t o = swz(r, (uint32_t)(kk * 2 + bChk));
                LDSM4(bHi[p], stOff + B_HI + o);
                LDSM4(bLo[p], stOff + B_LO + o);
            }
            #pragma unroll
            for (int mt = 0; mt < 4; mt++)
                #pragma unroll
                for (int nt = 0; nt < 4; nt++)
                    MMA_BF16(acc[mt][nt], aHi[mt], bHi[nt >> 1][(nt & 1) * 2], bHi[nt >> 1][(nt & 1) * 2 + 1]);
            #pragma unroll
            for (int mt = 0; mt < 4; mt++)
                #pragma unroll
                for (int nt = 0; nt < 4; nt++)
                    MMA_BF16(acc[mt][nt], aLo[mt], bHi[nt >> 1][(nt & 1) * 2], bHi[nt >> 1][(nt & 1) * 2 + 1]);
            #pragma unroll
            for (int mt = 0; mt < 4; mt++)
                #pragma unroll
                for (int nt = 0; nt < 4; nt++)
                    MMA_BF16(acc[mt][nt], aHi[mt], bLo[nt >> 1][(nt & 1) * 2], bLo[nt >> 1][(nt & 1) * 2 + 1]);
        }
    }

    // epilogue
    int colB = wn * 32 + (lane & 3) * 2;
    float2 bv[4];
    #pragma unroll
    for (int nt = 0; nt < 4; nt++)
        bv[nt] = *(const float2*)(bias + n0 + colB + nt * 8);
    #pragma unroll
    for (int mt = 0; mt < 4; mt++) {
        int rr = mtB + wm * 64 + mt * 16 + (lane >> 2);
        #pragma unroll
        for (int h = 0; h < 2; h++) {
            int row = rr + h * 8;
            if (row < cnt) {
                int tok = list[row];
                float* dst = g_logits + (size_t)tok * 1024 + n0 + colB;
                #pragma unroll
                for (int nt = 0; nt < 4; nt++) {
                    float2 o;
                    o.x = acc[mt][nt][h * 2 + 0] + bv[nt].x;
                    o.y = acc[mt][nt][h * 2 + 1] + bv[nt].y;
                    *(float2*)(dst + nt * 8) = o;
                }
            }
        }
    }
    #undef ISSUE_STAGE
}

// per-token softmax + full-row output write
__global__ void __launch_bounds__(256) finalize_kernel(
    const int* __restrict__ pY, const int* __restrict__ Y,
    float* __restrict__ out)
{
    int n = blockIdx.x;
    int cls = pY[n];
    float ep = g_endprob[n];
    float* logp = out;
    float* row  = out + NTOK + (size_t)n * NCOLS;
    int tid = threadIdx.x;

    if (cls == 0) {
        #pragma unroll
        for (int i = 0; i < 8; i++) row[2 + tid + i * 256] = 0.f;
        if (tid == 0) { row[0] = ep; row[1] = ep; logp[n] = logf(ep); }
        return;
    }

    const float* lg = g_logits + (size_t)n * 1024;
    float v[4]; float vmax = -1e30f;
    #pragma unroll
    for (int i = 0; i < 4; i++) { v[i] = lg[tid + i * 256]; vmax = fmaxf(vmax, v[i]); }

    __shared__ float sred[8];
    #pragma unroll
    for (int o = 16; o > 0; o >>= 1) vmax = fmaxf(vmax, __shfl_xor_sync(0xffffffffu, vmax, o));
    if ((tid & 31) == 0) sred[tid >> 5] = vmax;
    __syncthreads();
    float m = fmaxf(fmaxf(fmaxf(sred[0], sred[1]), fmaxf(sred[2], sred[3])),
                    fmaxf(fmaxf(sred[4], sred[5]), fmaxf(sred[6], sred[7])));
    __syncthreads();

    float e[4]; float s = 0.f;
    #pragma unroll
    for (int i = 0; i < 4; i++) { e[i] = expf(v[i] - m); s += e[i]; }
    #pragma unroll
    for (int o = 16; o > 0; o >>= 1) s += __shfl_xor_sync(0xffffffffu, s, o);
    if ((tid & 31) == 0) sred[tid >> 5] = s;
    __syncthreads();
    float sum = sred[0] + sred[1] + sred[2] + sred[3]
              + sred[4] + sred[5] + sred[6] + sred[7];

    float nonend = 1.f - ep;
    float scale = nonend / sum;
    int off  = (cls == 1) ? 2 : (2 + FPN);
    int zoff = (cls == 1) ? (2 + FPN) : 2;
    #pragma unroll
    for (int i = 0; i < 4; i++) row[off + tid + i * 256] = e[i] * scale;
    #pragma unroll
    for (int i = 0; i < 4; i++) row[zoff + tid + i * 256] = 0.f;
    if (tid == 0) { row[0] = 0.f; row[1] = 0.f; }

    int idx = Y[n] - 2 - ((cls == 2) ? FPN : 0);
    idx = min(max(idx, 0), 1023);
    if (tid == (idx & 255)) {
        int i = idx >> 8;
        logp[n] = (v[i] - m - logf(sum)) + logf(nonend);
    }
}

extern "C" void kernel_launch(void* const* d_in, const int* in_sizes, int n_in,
                              void* d_out, int out_size)
{
    const float* X     = (const float*)d_in[0];
    const int*   pY    = (const int*)  d_in[1];
    const int*   Y     = (const int*)  d_in[2];
    const float* W_end = (const float*)d_in[3];
    const float* b_end = (const float*)d_in[4];
    const float* W_hcw = (const float*)d_in[5];
    const float* b_hcw = (const float*)d_in[6];
    const float* W_roo = (const float*)d_in[7];
    const float* b_roo = (const float*)d_in[8];
    float* out = (float*)d_out;

    cudaFuncSetAttribute(gemm_mma_kernel,
                         cudaFuncAttributeMaxDynamicSharedMemorySize, SM_TOTAL);

    init_kernel<<<1, 32>>>();
    wconvert_kernel<<<2 * FPN * HDIM / 4 / 256, 256>>>(W_hcw, W_roo);
    classify_convert_kernel<<<NTOK / 8, 256>>>(X, pY, W_end, b_end);
    dim3 grid(FPN / BN, NTOK / BM, 2);
    gemm_mma_kernel<<<grid, 256, SM_TOTAL>>>(b_hcw, b_roo);
    finalize_kernel<<<NTOK, 256>>>(pY, Y, out);
}

// round 6
// speedup vs baseline: 3.8402x; 1.1212x over previous
#include <cuda_runtime.h>
#include <cuda_fp16.h>
#include <cstdint>
#include <math.h>

#define NTOK 16384
#define HDIM 2048
#define FPN  1024
#define NCOLS 2050

#define BM 128
#define BN 128
#define BK 32
#define KIT (HDIM / BK)   // 64
#define STAGES 4

// per-stage smem: 3 tiles x 128 rows x 64B (XOR-swizzled 16B chunks)
#define A_HI 0
#define B_HI 8192
#define B_LO 16384
#define STG  24576
#define SM_TOTAL (STAGES * STG)   // 98304 B -> 2 CTAs/SM

// scratch (static device mem only)
__device__ float   g_logits[(size_t)NTOK * 1024];     // 64 MB
__device__ __half  g_Xh [(size_t)NTOK * HDIM];        // 64 MB
__device__ __half  g_Whi[(size_t)2 * FPN * HDIM];     // 8 MB
__device__ __half  g_Wlo[(size_t)2 * FPN * HDIM];     // 8 MB
__device__ int     g_list[2][NTOK];
__device__ int     g_cnt[2];
__device__ int     g_tile;
__device__ float   g_endprob[NTOK];

__device__ __forceinline__ uint32_t smem_u32(const void* p) {
    uint32_t a;
    asm("{ .reg .u64 t; cvta.to.shared.u64 t, %1; cvt.u32.u64 %0, t; }" : "=r"(a) : "l"(p));
    return a;
}

#define CP16(dst, src) \
    asm volatile("cp.async.cg.shared.global [%0], [%1], 16;" :: "r"(dst), "l"(src))
#define CP_COMMIT() asm volatile("cp.async.commit_group;" ::: "memory")
#define CP_WAIT2()  asm volatile("cp.async.wait_group 2;" ::: "memory")

#define LDSM4(r, addr) \
    asm volatile("ldmatrix.sync.aligned.m8n8.x4.shared.b16 {%0,%1,%2,%3}, [%4];" \
        : "=r"((r)[0]), "=r"((r)[1]), "=r"((r)[2]), "=r"((r)[3]) : "r"(addr))

#define MMA_F16(c, a, b0, b1) \
    asm volatile("mma.sync.aligned.m16n8k16.row.col.f32.f16.f16.f32 " \
        "{%0,%1,%2,%3}, {%4,%5,%6,%7}, {%8,%9}, {%0,%1,%2,%3};" \
        : "+f"((c)[0]), "+f"((c)[1]), "+f"((c)[2]), "+f"((c)[3]) \
        : "r"((a)[0]), "r"((a)[1]), "r"((a)[2]), "r"((a)[3]), "r"(b0), "r"(b1))

// swizzled byte offset inside a 128x64B tile
__device__ __forceinline__ uint32_t swz(uint32_t row, uint32_t chunk) {
    return row * 64u + ((chunk ^ ((row >> 1) & 3u)) << 4);
}

__device__ __forceinline__ uint2 cvt4h(float4 v) {
    __half2 h01 = __floats2half2_rn(v.x, v.y);
    __half2 h23 = __floats2half2_rn(v.z, v.w);
    return make_uint2(*(uint32_t*)&h01, *(uint32_t*)&h23);
}
__device__ __forceinline__ void split4h(float4 v, uint2& hi, uint2& lo) {
    __half2 h01 = __floats2half2_rn(v.x, v.y);
    __half2 h23 = __floats2half2_rn(v.z, v.w);
    float2 f01 = __half22float2(h01), f23 = __half22float2(h23);
    __half2 l01 = __floats2half2_rn(v.x - f01.x, v.y - f01.y);
    __half2 l23 = __floats2half2_rn(v.z - f23.x, v.w - f23.y);
    hi = make_uint2(*(uint32_t*)&h01, *(uint32_t*)&h23);
    lo = make_uint2(*(uint32_t*)&l01, *(uint32_t*)&l23);
}

// ---------------- kernels ----------------
__global__ void init_kernel() {
    if (threadIdx.x < 2) g_cnt[threadIdx.x] = 0;
    if (threadIdx.x == 2) g_tile = 0;
}

// end-head dot + sigmoid + compaction + X fp16 conversion
__global__ void __launch_bounds__(256) classify_convert_kernel(
    const float* __restrict__ X, const int* __restrict__ pY,
    const float* __restrict__ W_end, const float* __restrict__ b_end)
{
    int gwarp = (blockIdx.x * blockDim.x + threadIdx.x) >> 5;
    int lane  = threadIdx.x & 31;
    if (gwarp >= NTOK) return;
    const float4* x = reinterpret_cast<const float4*>(X) + (size_t)gwarp * (HDIM / 4);
    const float4* w = reinterpret_cast<const float4*>(W_end);
    uint2* xh = reinterpret_cast<uint2*>(g_Xh + (size_t)gwarp * HDIM);
    float acc = 0.f;
    #pragma unroll 4
    for (int i = lane; i < HDIM / 4; i += 32) {
        float4 a = x[i]; float4 b = w[i];
        acc = fmaf(a.x, b.x, acc); acc = fmaf(a.y, b.y, acc);
        acc = fmaf(a.z, b.z, acc); acc = fmaf(a.w, b.w, acc);
        xh[i] = cvt4h(a);
    }
    #pragma unroll
    for (int o = 16; o > 0; o >>= 1) acc += __shfl_xor_sync(0xffffffffu, acc, o);
    if (lane == 0) {
        float logit = acc + b_end[0];
        float ep = 1.f / (1.f + expf(-logit));
        g_endprob[gwarp] = ep;
        int c = pY[gwarp];
        if (c == 1 || c == 2) {
            int pos = atomicAdd(&g_cnt[c - 1], 1);
            g_list[c - 1][pos] = gwarp;
        }
    }
}

__global__ void __launch_bounds__(256) wconvert_kernel(
    const float* __restrict__ W0, const float* __restrict__ W1)
{
    int i = blockIdx.x * blockDim.x + threadIdx.x;   // float4 index
    const int half = FPN * HDIM / 4;
    const float4* src = (i < half) ? (const float4*)W0 + i : (const float4*)W1 + (i - half);
    float4 v = *src;
    uint2 hi, lo; split4h(v, hi, lo);
    reinterpret_cast<uint2*>(g_Whi)[i] = hi;
    reinterpret_cast<uint2*>(g_Wlo)[i] = lo;
}

// Persistent gathered fp16 2-pass GEMM; cp.async 4-stage pipeline; 2 CTAs/SM.
__global__ void __launch_bounds__(256, 2) gemm_mma_kernel(
    const float* __restrict__ b0, const float* __restrict__ b1)
{
    extern __shared__ char smem[];
    __shared__ int s_tile;
    uint32_t sb = smem_u32(smem);
    int tid = threadIdx.x;
    int lane = tid & 31, wid = tid >> 5;
    int wm = wid >> 2, wn = wid & 3;     // warp grid 2 x 4; warp tile 64 x 32

    int cnt0 = g_cnt[0], cnt1 = g_cnt[1];
    int tiles0 = (cnt0 + BM - 1) / BM, tiles1 = (cnt1 + BM - 1) / BM;
    int total = (tiles0 + tiles1) * 8;

    int c  = tid & 3;
    int r0 = tid >> 2;
    int sub = lane >> 3, r8 = lane & 7;
    int aRowL = (sub & 1) * 8 + r8, aChk = sub >> 1;
    int bRowL = (sub >> 1) * 8 + r8, bChk = sub & 1;

    while (true) {
        if (tid == 0) s_tile = atomicAdd(&g_tile, 1);
        __syncthreads();
        int t = s_tile;
        if (t >= total) break;

        int sel, u, cnt;
        if (t < tiles0 * 8) { sel = 0; u = t; cnt = cnt0; }
        else                { sel = 1; u = t - tiles0 * 8; cnt = cnt1; }
        int mtB = (u >> 3) * BM;          // 8 consecutive tiles share A
        int n0  = (u & 7) * BN;
        const float* bias = sel ? b1 : b0;
        const int*   list = g_list[sel];

        const __half* pA[2];
        const __half* pBhi[2];
        const __half* pBlo[2];
        uint32_t dOff[2];
        #pragma unroll
        for (int j = 0; j < 2; j++) {
            int r = r0 + j * 64;
            int m = mtB + r;
            int tok = list[m < cnt ? m : cnt - 1];
            pA[j] = g_Xh + (size_t)tok * HDIM + c * 8;
            size_t wo = (size_t)sel * FPN * HDIM + (size_t)(n0 + r) * HDIM + c * 8;
            pBhi[j] = g_Whi + wo;
            pBlo[j] = g_Wlo + wo;
            dOff[j] = swz((uint32_t)r, (uint32_t)c);
        }

        float acc[4][4][4];
        #pragma unroll
        for (int i = 0; i < 4; i++)
            #pragma unroll
            for (int j = 0; j < 4; j++)
                #pragma unroll
                for (int q = 0; q < 4; q++) acc[i][j][q] = 0.f;

        #define ISSUE_STAGE(stage, k0)                                          \
            do {                                                                \
                uint32_t st_ = sb + (uint32_t)(stage) * STG;                    \
                _Pragma("unroll")                                               \
                for (int j_ = 0; j_ < 2; j_++) {                                \
                    uint32_t d_ = st_ + dOff[j_];                               \
                    CP16(d_ + A_HI, pA[j_] + (k0));                             \
                    CP16(d_ + B_HI, pBhi[j_] + (k0));                           \
                    CP16(d_ + B_LO, pBlo[j_] + (k0));                           \
                }                                                               \
                CP_COMMIT();                                                    \
            } while (0)

        ISSUE_STAGE(0, 0);
        ISSUE_STAGE(1, BK);
        ISSUE_STAGE(2, 2 * BK);

        for (int it = 0; it < KIT; it++) {
            CP_WAIT2();
            __syncthreads();
            int ld = it + STAGES - 1;
            if (ld < KIT) {
                ISSUE_STAGE(ld & 3, ld * BK);
            } else {
                CP_COMMIT();
            }
            uint32_t stOff = sb + (uint32_t)(it & 3) * STG;

            #pragma unroll
            for (int kk = 0; kk < 2; kk++) {
                uint32_t aHi[4][4], bHi[2][4], bLo[2][4];
                #pragma unroll
                for (int mt = 0; mt < 4; mt++) {
                    uint32_t r = (uint32_t)(wm * 64 + mt * 16 + aRowL);
                    LDSM4(aHi[mt], stOff + A_HI + swz(r, (uint32_t)(kk * 2 + aChk)));
                }
                #pragma unroll
                for (int p = 0; p < 2; p++) {
                    uint32_t r = (uint32_t)(wn * 32 + p * 16 + bRowL);
                    uint32_t o = swz(r, (uint32_t)(kk * 2 + bChk));
                    LDSM4(bHi[p], stOff + B_HI + o);
                    LDSM4(bLo[p], stOff + B_LO + o);
                }
                #pragma unroll
                for (int mt = 0; mt < 4; mt++)
                    #pragma unroll
                    for (int nt = 0; nt < 4; nt++)
                        MMA_F16(acc[mt][nt], aHi[mt], bHi[nt >> 1][(nt & 1) * 2], bHi[nt >> 1][(nt & 1) * 2 + 1]);
                #pragma unroll
                for (int mt = 0; mt < 4; mt++)
                    #pragma unroll
                    for (int nt = 0; nt < 4; nt++)
                        MMA_F16(acc[mt][nt], aHi[mt], bLo[nt >> 1][(nt & 1) * 2], bLo[nt >> 1][(nt & 1) * 2 + 1]);
            }
        }

        // epilogue
        int colB = wn * 32 + (lane & 3) * 2;
        float2 bv[4];
        #pragma unroll
        for (int nt = 0; nt < 4; nt++)
            bv[nt] = *(const float2*)(bias + n0 + colB + nt * 8);
        #pragma unroll
        for (int mt = 0; mt < 4; mt++) {
            int rr = mtB + wm * 64 + mt * 16 + (lane >> 2);
            #pragma unroll
            for (int h = 0; h < 2; h++) {
                int row = rr + h * 8;
                if (row < cnt) {
                    int tok = list[row];
                    float* dst = g_logits + (size_t)tok * 1024 + n0 + colB;
                    #pragma unroll
                    for (int nt = 0; nt < 4; nt++) {
                        float2 o;
                        o.x = acc[mt][nt][h * 2 + 0] + bv[nt].x;
                        o.y = acc[mt][nt][h * 2 + 1] + bv[nt].y;
                        *(float2*)(dst + nt * 8) = o;
                    }
                }
            }
        }
        #undef ISSUE_STAGE
    }
}

// per-token softmax + full-row output write
__global__ void __launch_bounds__(256) finalize_kernel(
    const int* __restrict__ pY, const int* __restrict__ Y,
    float* __restrict__ out)
{
    int n = blockIdx.x;
    int cls = pY[n];
    float ep = g_endprob[n];
    float* logp = out;
    float* row  = out + NTOK + (size_t)n * NCOLS;
    int tid = threadIdx.x;

    if (cls == 0) {
        #pragma unroll
        for (int i = 0; i < 8; i++) row[2 + tid + i * 256] = 0.f;
        if (tid == 0) { row[0] = ep; row[1] = ep; logp[n] = logf(ep); }
        return;
    }

    const float* lg = g_logits + (size_t)n * 1024;
    float v[4]; float vmax = -1e30f;
    #pragma unroll
    for (int i = 0; i < 4; i++) { v[i] = lg[tid + i * 256]; vmax = fmaxf(vmax, v[i]); }

    __shared__ float sred[8];
    #pragma unroll
    for (int o = 16; o > 0; o >>= 1) vmax = fmaxf(vmax, __shfl_xor_sync(0xffffffffu, vmax, o));
    if ((tid & 31) == 0) sred[tid >> 5] = vmax;
    __syncthreads();
    float m = fmaxf(fmaxf(fmaxf(sred[0], sred[1]), fmaxf(sred[2], sred[3])),
                    fmaxf(fmaxf(sred[4], sred[5]), fmaxf(sred[6], sred[7])));
    __syncthreads();

    float e[4]; float s = 0.f;
    #pragma unroll
    for (int i = 0; i < 4; i++) { e[i] = expf(v[i] - m); s += e[i]; }
    #pragma unroll
    for (int o = 16; o > 0; o >>= 1) s += __shfl_xor_sync(0xffffffffu, s, o);
    if ((tid & 31) == 0) sred[tid >> 5] = s;
    __syncthreads();
    float sum = sred[0] + sred[1] + sred[2] + sred[3]
              + sred[4] + sred[5] + sred[6] + sred[7];

    float nonend = 1.f - ep;
    float scale = nonend / sum;
    int off  = (cls == 1) ? 2 : (2 + FPN);
    int zoff = (cls == 1) ? (2 + FPN) : 2;
    #pragma unroll
    for (int i = 0; i < 4; i++) row[off + tid + i * 256] = e[i] * scale;
    #pragma unroll
    for (int i = 0; i < 4; i++) row[zoff + tid + i * 256] = 0.f;
    if (tid == 0) { row[0] = 0.f; row[1] = 0.f; }

    int idx = Y[n] - 2 - ((cls == 2) ? FPN : 0);
    idx = min(max(idx, 0), 1023);
    if (tid == (idx & 255)) {
        int i = idx >> 8;
        logp[n] = (v[i] - m - logf(sum)) + logf(nonend);
    }
}

extern "C" void kernel_launch(void* const* d_in, const int* in_sizes, int n_in,
                              void* d_out, int out_size)
{
    const float* X     = (const float*)d_in[0];
    const int*   pY    = (const int*)  d_in[1];
    const int*   Y     = (const int*)  d_in[2];
    const float* W_end = (const float*)d_in[3];
    const float* b_end = (const float*)d_in[4];
    const float* W_hcw = (const float*)d_in[5];
    const float* b_hcw = (const float*)d_in[6];
    const float* W_roo = (const float*)d_in[7];
    const float* b_roo = (const float*)d_in[8];
    float* out = (float*)d_out;

    cudaFuncSetAttribute(gemm_mma_kernel,
                         cudaFuncAttributeMaxDynamicSharedMemorySize, SM_TOTAL);

    init_kernel<<<1, 32>>>();
    wconvert_kernel<<<2 * FPN * HDIM / 4 / 256, 256>>>(W_hcw, W_roo);
    classify_convert_kernel<<<NTOK / 8, 256>>>(X, pY, W_end, b_end);
    gemm_mma_kernel<<<304, 256, SM_TOTAL>>>(b_hcw, b_roo);   // persistent, 2 CTAs/SM
    finalize_kernel<<<NTOK, 256>>>(pY, Y, out);
}

// round 7
// speedup vs baseline: 6.2889x; 1.6377x over previous
#include <cuda_runtime.h>
#include <cuda_fp16.h>
#include <cstdint>
#include <math.h>

#define NTOK 16384
#define HDIM 2048
#define FPN  1024
#define NCOLS 2050

#define BM 128
#define BN 128
#define BK 64
#define KIT (HDIM / BK)   // 32
#define STAGES 3

// per-stage smem: A(128x64 half =16KB) + B(16KB); 128B rows, XOR-swizzled 16B chunks
#define A_OFF 0
#define B_OFF 16384
#define STG   32768
#define SM_TOTAL (STAGES * STG)   // 98304 -> 2 CTAs/SM

// scratch (static device mem only)
__device__ float   g_logits[(size_t)NTOK * 1024];     // 64 MB
__device__ __half  g_Xh[(size_t)NTOK * HDIM];         // 64 MB
__device__ __half  g_Wh[(size_t)2 * FPN * HDIM];      // 8 MB
__device__ int     g_list[2][NTOK];
__device__ int     g_cnt[2];
__device__ int     g_tile;
__device__ float   g_endprob[NTOK];

__device__ __forceinline__ uint32_t smem_u32(const void* p) {
    uint32_t a;
    asm("{ .reg .u64 t; cvta.to.shared.u64 t, %1; cvt.u32.u64 %0, t; }" : "=r"(a) : "l"(p));
    return a;
}

#define CP16(dst, src) \
    asm volatile("cp.async.cg.shared.global [%0], [%1], 16;" :: "r"(dst), "l"(src))
#define CP_COMMIT() asm volatile("cp.async.commit_group;" ::: "memory")
#define CP_WAIT1()  asm volatile("cp.async.wait_group 1;" ::: "memory")

#define LDSM4(r, addr) \
    asm volatile("ldmatrix.sync.aligned.m8n8.x4.shared.b16 {%0,%1,%2,%3}, [%4];" \
        : "=r"((r)[0]), "=r"((r)[1]), "=r"((r)[2]), "=r"((r)[3]) : "r"(addr))

#define MMA_F16(c, a, b0, b1) \
    asm volatile("mma.sync.aligned.m16n8k16.row.col.f32.f16.f16.f32 " \
        "{%0,%1,%2,%3}, {%4,%5,%6,%7}, {%8,%9}, {%0,%1,%2,%3};" \
        : "+f"((c)[0]), "+f"((c)[1]), "+f"((c)[2]), "+f"((c)[3]) \
        : "r"((a)[0]), "r"((a)[1]), "r"((a)[2]), "r"((a)[3]), "r"(b0), "r"(b1))

// swizzled byte offset inside a 128-row x 128B tile (8 chunks/row, XOR by row&7)
__device__ __forceinline__ uint32_t swz(uint32_t row, uint32_t chunk) {
    return row * 128u + ((chunk ^ (row & 7u)) << 4);
}

__device__ __forceinline__ uint2 cvt4h(float4 v) {
    __half2 h01 = __floats2half2_rn(v.x, v.y);
    __half2 h23 = __floats2half2_rn(v.z, v.w);
    return make_uint2(*(uint32_t*)&h01, *(uint32_t*)&h23);
}

// ---------------- kernels ----------------
__global__ void init_kernel() {
    if (threadIdx.x < 2) g_cnt[threadIdx.x] = 0;
    if (threadIdx.x == 2) g_tile = 0;
}

__global__ void __launch_bounds__(256) classify_convert_kernel(
    const float* __restrict__ X, const int* __restrict__ pY,
    const float* __restrict__ W_end, const float* __restrict__ b_end)
{
    int gwarp = (blockIdx.x * blockDim.x + threadIdx.x) >> 5;
    int lane  = threadIdx.x & 31;
    if (gwarp >= NTOK) return;
    const float4* x = reinterpret_cast<const float4*>(X) + (size_t)gwarp * (HDIM / 4);
    const float4* w = reinterpret_cast<const float4*>(W_end);
    uint2* xh = reinterpret_cast<uint2*>(g_Xh + (size_t)gwarp * HDIM);
    float acc = 0.f;
    #pragma unroll 4
    for (int i = lane; i < HDIM / 4; i += 32) {
        float4 a = x[i]; float4 b = w[i];
        acc = fmaf(a.x, b.x, acc); acc = fmaf(a.y, b.y, acc);
        acc = fmaf(a.z, b.z, acc); acc = fmaf(a.w, b.w, acc);
        xh[i] = cvt4h(a);
    }
    #pragma unroll
    for (int o = 16; o > 0; o >>= 1) acc += __shfl_xor_sync(0xffffffffu, acc, o);
    if (lane == 0) {
        float logit = acc + b_end[0];
        float ep = 1.f / (1.f + expf(-logit));
        g_endprob[gwarp] = ep;
        int c = pY[gwarp];
        if (c == 1 || c == 2) {
            int pos = atomicAdd(&g_cnt[c - 1], 1);
            g_list[c - 1][pos] = gwarp;
        }
    }
}

__global__ void __launch_bounds__(256) wconvert_kernel(
    const float* __restrict__ W0, const float* __restrict__ W1)
{
    int i = blockIdx.x * blockDim.x + threadIdx.x;
    const int half = FPN * HDIM / 4;
    const float4* src = (i < half) ? (const float4*)W0 + i : (const float4*)W1 + (i - half);
    reinterpret_cast<uint2*>(g_Wh)[i] = cvt4h(*src);
}

// Persistent single-pass fp16 gathered GEMM; BK=64, 3-stage; cross-tile prefetch.
__global__ void __launch_bounds__(256, 2) gemm_mma_kernel(
    const float* __restrict__ b0, const float* __restrict__ b1)
{
    extern __shared__ char smem[];
    __shared__ int s_tile;
    uint32_t sb = smem_u32(smem);
    int tid = threadIdx.x;
    int lane = tid & 31, wid = tid >> 5;
    int wm = wid >> 2, wn = wid & 3;     // warp grid 2 x 4; warp tile 64 x 32

    int cnt0 = g_cnt[0], cnt1 = g_cnt[1];
    int tiles0 = (cnt0 + BM - 1) / BM, tiles1 = (cnt1 + BM - 1) / BM;
    int total = (tiles0 + tiles1) * 8;

    int c  = tid & 7;                    // 16B chunk 0..7 within 128B row
    int r0 = tid >> 3;                   // 0..31; rows r0 + j*32
    int sub = lane >> 3, r8 = lane & 7;
    int aRowL = (sub & 1) * 8 + r8, aChk = sub >> 1;
    int bRowL = (sub >> 1) * 8 + r8, bChk = sub & 1;

    // current tile state
    const __half* pA[4];
    const __half* pB[4];
    uint32_t dOff[4];
    int selC, mtC, n0C, cntC;

    #define SETUP(t)                                                            \
        do {                                                                    \
            int u_;                                                             \
            if ((t) < tiles0 * 8) { selC = 0; u_ = (t);              cntC = cnt0; } \
            else                  { selC = 1; u_ = (t) - tiles0 * 8; cntC = cnt1; } \
            mtC = (u_ >> 3) * BM;                                               \
            n0C = (u_ & 7) * BN;                                                \
            const int* list_ = g_list[selC];                                    \
            _Pragma("unroll")                                                   \
            for (int j_ = 0; j_ < 4; j_++) {                                    \
                int r_ = r0 + j_ * 32;                                          \
                int m_ = mtC + r_;                                              \
                int tok_ = list_[m_ < cntC ? m_ : cntC - 1];                    \
                pA[j_] = g_Xh + (size_t)tok_ * HDIM + c * 8;                    \
                pB[j_] = g_Wh + (size_t)selC * FPN * HDIM                       \
                              + (size_t)(n0C + r_) * HDIM + c * 8;              \
                dOff[j_] = swz((uint32_t)r_, (uint32_t)c);                      \
            }                                                                   \
        } while (0)

    #define ISSUE_STAGE(stage, k0)                                              \
        do {                                                                    \
            uint32_t st_ = sb + (uint32_t)(stage) * STG;                        \
            _Pragma("unroll")                                                   \
            for (int j_ = 0; j_ < 4; j_++) {                                    \
                CP16(st_ + A_OFF + dOff[j_], pA[j_] + (k0));                    \
                CP16(st_ + B_OFF + dOff[j_], pB[j_] + (k0));                    \
            }                                                                   \
            CP_COMMIT();                                                        \
        } while (0)

    if (tid == 0) s_tile = atomicAdd(&g_tile, 1);
    __syncthreads();
    int t = s_tile;
    if (t >= total) return;
    SETUP(t);
    ISSUE_STAGE(0, 0);
    ISSUE_STAGE(1, BK);

    float acc[4][4][4];
    #pragma unroll
    for (int i = 0; i < 4; i++)
        #pragma unroll
        for (int j = 0; j < 4; j++)
            #pragma unroll
            for (int q = 0; q < 4; q++) acc[i][j][q] = 0.f;

    while (true) {
        // ---- mainloop over K ----
        for (int it = 0; it < KIT; it++) {
            CP_WAIT1();
            __syncthreads();
            int ld = it + STAGES - 1;
            if (ld < KIT) {
                ISSUE_STAGE(ld % STAGES, ld * BK);
            } else {
                CP_COMMIT();
            }
            uint32_t stOff = sb + (uint32_t)(it % STAGES) * STG;

            #pragma unroll
            for (int kk = 0; kk < 4; kk++) {
                uint32_t aF[4][4], bF[2][4];
                #pragma unroll
                for (int mt = 0; mt < 4; mt++) {
                    uint32_t r = (uint32_t)(wm * 64 + mt * 16 + aRowL);
                    LDSM4(aF[mt], stOff + A_OFF + swz(r, (uint32_t)(kk * 2 + aChk)));
                }
                #pragma unroll
                for (int p = 0; p < 2; p++) {
                    uint32_t r = (uint32_t)(wn * 32 + p * 16 + bRowL);
                    LDSM4(bF[p], stOff + B_OFF + swz(r, (uint32_t)(kk * 2 + bChk)));
                }
                #pragma unroll
                for (int mt = 0; mt < 4; mt++)
                    #pragma unroll
                    for (int nt = 0; nt < 4; nt++)
                        MMA_F16(acc[mt][nt], aF[mt],
                                bF[nt >> 1][(nt & 1) * 2], bF[nt >> 1][(nt & 1) * 2 + 1]);
            }
        }

        // ---- save old-tile info, fetch + prefetch next tile ----
        int selO = selC, mtO = mtC, n0O = n0C, cntO = cntC;
        if (tid == 0) s_tile = atomicAdd(&g_tile, 1);
        __syncthreads();             // also guards stage reuse vs last reads
        int tn = s_tile;
        if (tn < total) {
            SETUP(tn);
            ISSUE_STAGE(0, 0);
            ISSUE_STAGE(1, BK);
        }

        // ---- epilogue for old tile (overlaps next tile's loads) ----
        {
            const float* bias = selO ? b1 : b0;
            const int*   list = g_list[selO];
            int colB = wn * 32 + (lane & 3) * 2;
            float2 bv[4];
            #pragma unroll
            for (int nt = 0; nt < 4; nt++)
                bv[nt] = *(const float2*)(bias + n0O + colB + nt * 8);
            #pragma unroll
            for (int mt = 0; mt < 4; mt++) {
                int rr = mtO + wm * 64 + mt * 16 + (lane >> 2);
                #pragma unroll
                for (int h = 0; h < 2; h++) {
                    int row = rr + h * 8;
                    if (row < cntO) {
                        int tok = list[row];
                        float* dst = g_logits + (size_t)tok * 1024 + n0O + colB;
                        #pragma unroll
                        for (int nt = 0; nt < 4; nt++) {
                            float2 o;
                            o.x = acc[mt][nt][h * 2 + 0] + bv[nt].x;
                            o.y = acc[mt][nt][h * 2 + 1] + bv[nt].y;
                            *(float2*)(dst + nt * 8) = o;
                        }
                    }
                }
            }
        }
        if (tn >= total) break;
        #pragma unroll
        for (int i = 0; i < 4; i++)
            #pragma unroll
            for (int j = 0; j < 4; j++)
                #pragma unroll
                for (int q = 0; q < 4; q++) acc[i][j][q] = 0.f;
    }
    #undef ISSUE_STAGE
    #undef SETUP
}

// per-token softmax + full-row output write
__global__ void __launch_bounds__(256) finalize_kernel(
    const int* __restrict__ pY, const int* __restrict__ Y,
    float* __restrict__ out)
{
    int n = blockIdx.x;
    int cls = pY[n];
    float ep = g_endprob[n];
    float* logp = out;
    float* row  = out + NTOK + (size_t)n * NCOLS;
    int tid = threadIdx.x;

    if (cls == 0) {
        #pragma unroll
        for (int i = 0; i < 8; i++) row[2 + tid + i * 256] = 0.f;
        if (tid == 0) { row[0] = ep; row[1] = ep; logp[n] = logf(ep); }
        return;
    }

    const float* lg = g_logits + (size_t)n * 1024;
    float v[4]; float vmax = -1e30f;
    #pragma unroll
    for (int i = 0; i < 4; i++) { v[i] = lg[tid + i * 256]; vmax = fmaxf(vmax, v[i]); }

    __shared__ float sred[8];
    #pragma unroll
    for (int o = 16; o > 0; o >>= 1) vmax = fmaxf(vmax, __shfl_xor_sync(0xffffffffu, vmax, o));
    if ((tid & 31) == 0) sred[tid >> 5] = vmax;
    __syncthreads();
    float m = fmaxf(fmaxf(fmaxf(sred[0], sred[1]), fmaxf(sred[2], sred[3])),
                    fmaxf(fmaxf(sred[4], sred[5]), fmaxf(sred[6], sred[7])));
    __syncthreads();

    float e[4]; float s = 0.f;
    #pragma unroll
    for (int i = 0; i < 4; i++) { e[i] = expf(v[i] - m); s += e[i]; }
    #pragma unroll
    for (int o = 16; o > 0; o >>= 1) s += __shfl_xor_sync(0xffffffffu, s, o);
    if ((tid & 31) == 0) sred[tid >> 5] = s;
    __syncthreads();
    float sum = sred[0] + sred[1] + sred[2] + sred[3]
              + sred[4] + sred[5] + sred[6] + sred[7];

    float nonend = 1.f - ep;
    float scale = nonend / sum;
    int off  = (cls == 1) ? 2 : (2 + FPN);
    int zoff = (cls == 1) ? (2 + FPN) : 2;
    #pragma unroll
    for (int i = 0; i < 4; i++) row[off + tid + i * 256] = e[i] * scale;
    #pragma unroll
    for (int i = 0; i < 4; i++) row[zoff + tid + i * 256] = 0.f;
    if (tid == 0) { row[0] = 0.f; row[1] = 0.f; }

    int idx = Y[n] - 2 - ((cls == 2) ? FPN : 0);
    idx = min(max(idx, 0), 1023);
    if (tid == (idx & 255)) {
        int i = idx >> 8;
        logp[n] = (v[i] - m - logf(sum)) + logf(nonend);
    }
}

extern "C" void kernel_launch(void* const* d_in, const int* in_sizes, int n_in,
                              void* d_out, int out_size)
{
    const float* X     = (const float*)d_in[0];
    const int*   pY    = (const int*)  d_in[1];
    const int*   Y     = (const int*)  d_in[2];
    const float* W_end = (const float*)d_in[3];
    const float* b_end = (const float*)d_in[4];
    const float* W_hcw = (const float*)d_in[5];
    const float* b_hcw = (const float*)d_in[6];
    const float* W_roo = (const float*)d_in[7];
    const float* b_roo = (const float*)d_in[8];
    float* out = (float*)d_out;

    cudaFuncSetAttribute(gemm_mma_kernel,
                         cudaFuncAttributeMaxDynamicSharedMemorySize, SM_TOTAL);

    init_kernel<<<1, 32>>>();
    wconvert_kernel<<<2 * FPN * HDIM / 4 / 256, 256>>>(W_hcw, W_roo);
    classify_convert_kernel<<<NTOK / 8, 256>>>(X, pY, W_end, b_end);
    gemm_mma_kernel<<<304, 256, SM_TOTAL>>>(b_hcw, b_roo);   // persistent, 2 CTAs/SM
    finalize_kernel<<<NTOK, 256>>>(pY, Y, out);
}